// round 10
// baseline (speedup 1.0000x reference)
#include <cuda_runtime.h>
#include <cuda_fp16.h>
#include <cstdint>
#include <cstddef>

// Problem constants
#define M_DIM 8192
#define K_DIM 4096
#define N_DIM 11008
#define NPACK (N_DIM / 8)
#define KPACK (K_DIM / 8)

// GEMM tiling: block 128x128x32, 8 warps (2M x 4N), warp tile 64x32
#define BM 128
#define BN 128
#define BK 32
#define NT (K_DIM / BK)        // 128
#define A_LD 40                // halves per A row (80B, conflict-free ldmatrix)
#define TK32 (K_DIM / 32)      // 128 k32-tiles
#define TN8 (N_DIM / 8)        // 1376 n8-tiles

#define MT_TILES (M_DIM / BM)  // 64
#define NT_TILES (N_DIM / BN)  // 86

// Device scratch (allocation-free rule)
__device__ __half g_xh[(size_t)M_DIM * K_DIM];       // x in fp16 [M,K]
// W in mma-fragment order: [tn8][tk32][lane]{b0_k16a, b1_k16a, b0_k16b, b1_k16b}
// half offset = ((tn*TK32 + tk32)*32 + lane)*8 + j16*4 + regsel*2 + (k&1)
// where lane = 4*(n&7) + ((k&7)>>1), j16 = (k&31)>>4, regsel = (k&15)>>3
__device__ __half g_wf[(size_t)K_DIM * N_DIM];

// ---------------------------------------------------------------------------
// Kernel 0: x fp32 -> fp16
// ---------------------------------------------------------------------------
__global__ void convert_x(const float* __restrict__ x) {
    size_t i = ((size_t)blockIdx.x * 256 + threadIdx.x) * 8;
    float4 a = *(const float4*)(x + i);
    float4 b = *(const float4*)(x + i + 4);
    __half2 h0 = __floats2half2_rn(a.x, a.y);
    __half2 h1 = __floats2half2_rn(a.z, a.w);
    __half2 h2 = __floats2half2_rn(b.x, b.y);
    __half2 h3 = __floats2half2_rn(b.z, b.w);
    uint4 u;
    u.x = *(uint32_t*)&h0; u.y = *(uint32_t*)&h1;
    u.z = *(uint32_t*)&h2; u.w = *(uint32_t*)&h3;
    *(uint4*)(g_xh + i) = u;
}

// ---------------------------------------------------------------------------
// Kernel 1: dequant int4 GPTQ -> fp16 fragment-ordered W
// Thread (pr, n): k = pr*8 + j (j=0..7). For this thread:
//   tk32 = pr>>2, j16 = (pr>>1)&1, regsel = pr&1 (constant across j)
//   j pair (2p,2p+1) -> lane 4*(n&7)+p, halves +0,+1  => 4 half2 stores
// ---------------------------------------------------------------------------
__global__ void dequant_kernel(const int* __restrict__ qweight,
                               const int* __restrict__ qzeros,
                               const void* __restrict__ scales_raw) {
    int pr = blockIdx.y;                       // 0..511
    int n  = blockIdx.x * 256 + threadIdx.x;   // 43*256 == 11008
    int g  = pr >> 4;

    const float* sf = (const float*)scales_raw;
    float probe = sf[0];
    bool is_f32 = (probe > 5e-4f && probe < 5e-2f);

    uint32_t q  = (uint32_t)qweight[(size_t)pr * N_DIM + n];
    uint32_t zq = (uint32_t)qzeros[(size_t)g * NPACK + (n >> 3)];
    float z = (float)((zq >> (4 * (n & 7))) & 15u);
    float s = is_f32 ? sf[(size_t)g * N_DIM + n]
                     : __half2float(((const __half*)scales_raw)[(size_t)g * N_DIM + n]);

    int tn    = n >> 3;
    int tk32  = pr >> 2;
    int j16   = (pr >> 1) & 1;
    int regsel= pr & 1;
    size_t base = (((size_t)tn * TK32 + tk32) * 32 + 4 * (n & 7)) * 8
                  + j16 * 4 + regsel * 2;

#pragma unroll
    for (int p = 0; p < 4; p++) {
        float w0 = ((float)((q >> (8 * p))     & 15u) - z) * s;
        float w1 = ((float)((q >> (8 * p + 4)) & 15u) - z) * s;
        *(__half2*)(g_wf + base + (size_t)p * 8) = __floats2half2_rn(w0, w1);
    }
}

// ---------------------------------------------------------------------------
// PTX helpers (baseline PTX only)
// ---------------------------------------------------------------------------
__device__ __forceinline__ void ldmatrix_x4(uint32_t& r0, uint32_t& r1,
                                            uint32_t& r2, uint32_t& r3,
                                            uint32_t addr) {
    asm volatile("ldmatrix.sync.aligned.m8n8.x4.shared.b16 {%0,%1,%2,%3}, [%4];"
                 : "=r"(r0), "=r"(r1), "=r"(r2), "=r"(r3) : "r"(addr));
}
__device__ __forceinline__ void mma16816(float* c, const uint32_t* a,
                                         uint32_t b0, uint32_t b1) {
    asm volatile(
        "mma.sync.aligned.m16n8k16.row.col.f32.f16.f16.f32 "
        "{%0,%1,%2,%3}, {%4,%5,%6,%7}, {%8,%9}, {%0,%1,%2,%3};"
        : "+f"(c[0]), "+f"(c[1]), "+f"(c[2]), "+f"(c[3])
        : "r"(a[0]), "r"(a[1]), "r"(a[2]), "r"(a[3]), "r"(b0), "r"(b1));
}

// ---------------------------------------------------------------------------
// Kernel 2: HMMA GEMM. A via smem (double-buffered, one barrier/k-tile);
// B loaded straight from fragment-ordered global into mma registers.
// ---------------------------------------------------------------------------
__global__ __launch_bounds__(256, 2)
void gemm_kernel(float* __restrict__ out) {
    __shared__ __half As[2][BM * A_LD];

    const int tid  = threadIdx.x;
    const int lane = tid & 31;
    const int wid  = tid >> 5;
    const int warp_m = wid & 1;    // 0..1 (64 rows each)
    const int warp_n = wid >> 1;   // 0..3 (32 cols each)

    // 8-M-supertile rasterization keeps the B slice L2-resident per wave
    const int bid = blockIdx.x;
    const int grp = bid / (8 * NT_TILES);
    const int rem = bid % (8 * NT_TILES);
    const int mt  = grp * 8 + (rem & 7);
    const int nt  = rem >> 3;
    const int m0 = mt * BM;
    const int n0 = nt * BN;

    const __half* asrc = g_xh + (size_t)m0 * K_DIM;

    // B fragment pointers: one per nh, advance 512B (256 halves) per k-tile
    const int tn0 = (n0 >> 3) + warp_n * 4;
    const uint4* bptr[4];
#pragma unroll
    for (int nh = 0; nh < 4; nh++)
        bptr[nh] = (const uint4*)(g_wf +
                   (((size_t)(tn0 + nh) * TK32) * 32 + lane) * 8);

    // A load coords: 128 rows x 4 chunks of 16B, 2 per thread
    const int ar = tid >> 2, ac = tid & 3;
    uint4 areg[2];

    auto loadA = [&](int kt) {
        const int k0 = kt * BK;
#pragma unroll
        for (int i = 0; i < 2; i++)
            areg[i] = *(const uint4*)(asrc + (size_t)(ar + i * 64) * K_DIM + k0 + ac * 8);
    };
    auto storeA = [&](int buf) {
#pragma unroll
        for (int i = 0; i < 2; i++)
            *(uint4*)(&As[buf][(ar + i * 64) * A_LD + ac * 8]) = areg[i];
    };

    uint4 bf[2][4];
    auto loadB = [&](int kt, int buf) {
#pragma unroll
        for (int nh = 0; nh < 4; nh++)
            bf[buf][nh] = bptr[nh][(size_t)kt * 32];   // *16B = 512B per kt
    };

    float acc[4][4][4];
#pragma unroll
    for (int i = 0; i < 4; i++)
#pragma unroll
        for (int j = 0; j < 4; j++) {
            acc[i][j][0] = 0.f; acc[i][j][1] = 0.f;
            acc[i][j][2] = 0.f; acc[i][j][3] = 0.f;
        }

    const uint32_t sbase = (uint32_t)__cvta_generic_to_shared(&As[0][0]);

    auto compute = [&](int buf) {
        const uint32_t abase = sbase + buf * (BM * A_LD * 2);
#pragma unroll
        for (int ks = 0; ks < 2; ks++) {
            const int kk = ks * 16;
            uint32_t a[4][4];
#pragma unroll
            for (int mi = 0; mi < 4; mi++) {
                int row = warp_m * 64 + mi * 16 + (lane & 15);
                int col = kk + 8 * (lane >> 4);
                ldmatrix_x4(a[mi][0], a[mi][1], a[mi][2], a[mi][3],
                            abase + (row * A_LD + col) * 2);
            }
#pragma unroll
            for (int mi = 0; mi < 4; mi++)
#pragma unroll
                for (int nh = 0; nh < 4; nh++) {
                    uint32_t b0 = ks ? bf[buf][nh].z : bf[buf][nh].x;
                    uint32_t b1 = ks ? bf[buf][nh].w : bf[buf][nh].y;
                    mma16816(acc[mi][nh], a[mi], b0, b1);
                }
        }
    };

    // Prologue
    loadA(0); storeA(0); loadA(1); loadB(0, 0);
    __syncthreads();

    // Steady state: ONE barrier per k-tile
#pragma unroll 1
    for (int t = 0; t < NT; t++) {
        const int cur = t & 1, nxt = cur ^ 1;
        if (t + 1 < NT) { loadB(t + 1, nxt); storeA(nxt); }
        if (t + 2 < NT) loadA(t + 2);
        compute(cur);
        __syncthreads();
    }

    // Epilogue: round through fp16, write float2
    const int g4 = lane >> 2, t4 = lane & 3;
#pragma unroll
    for (int mi = 0; mi < 4; mi++) {
#pragma unroll
        for (int nh = 0; nh < 4; nh++) {
            int row = m0 + warp_m * 64 + mi * 16 + g4;
            int col = n0 + warp_n * 32 + nh * 8 + t4 * 2;
            float2 v0, v1;
            v0.x = __half2float(__float2half_rn(acc[mi][nh][0]));
            v0.y = __half2float(__float2half_rn(acc[mi][nh][1]));
            v1.x = __half2float(__float2half_rn(acc[mi][nh][2]));
            v1.y = __half2float(__float2half_rn(acc[mi][nh][3]));
            *(float2*)(out + (size_t)row * N_DIM + col)       = v0;
            *(float2*)(out + (size_t)(row + 8) * N_DIM + col) = v1;
        }
    }
}

// ---------------------------------------------------------------------------
extern "C" void kernel_launch(void* const* d_in, const int* in_sizes, int n_in,
                              void* d_out, int out_size) {
    const float* x       = (const float*)d_in[0];
    const int*   qweight = (const int*)d_in[1];
    const int*   qzeros  = (const int*)d_in[2];
    const void*  scales  = d_in[3];
    float* out = (float*)d_out;

    convert_x<<<16384, 256>>>(x);
    dequant_kernel<<<dim3(43, KPACK), 256>>>(qweight, qzeros, scales);

    gemm_kernel<<<MT_TILES * NT_TILES, 256>>>(out);
}

// round 12
// speedup vs baseline: 1.5477x; 1.5477x over previous
#include <cuda_runtime.h>
#include <cuda_fp16.h>
#include <cstdint>
#include <cstddef>

// Problem constants
#define M_DIM 8192
#define K_DIM 4096
#define N_DIM 11008
#define NPACK (N_DIM / 8)
#define KPACK (K_DIM / 8)

// GEMM tiling: block 128x128x32, 8 warps (2M x 4N), warp tile 64x32
#define BM 128
#define BN 128
#define BK 32
#define NT (K_DIM / BK)        // 128
#define A_LD 40                // halves per A row (80B, conflict-free ldmatrix)
#define TK32 (K_DIM / 32)      // 128 k32-tiles

#define MT_TILES (M_DIM / BM)  // 64
#define NT_TILES (N_DIM / BN)  // 86

// Device scratch (allocation-free rule)
__device__ __half g_xh[(size_t)M_DIM * K_DIM];       // x in fp16 [M,K]
// W in mma-fragment order: [tn8][tk32][lane]{b0_k16a, b1_k16a, b0_k16b, b1_k16b}
__device__ __half g_wf[(size_t)K_DIM * N_DIM];

// ---------------------------------------------------------------------------
// Kernel 0: x fp32 -> fp16
// ---------------------------------------------------------------------------
__global__ void convert_x(const float* __restrict__ x) {
    size_t i = ((size_t)blockIdx.x * 256 + threadIdx.x) * 8;
    float4 a = *(const float4*)(x + i);
    float4 b = *(const float4*)(x + i + 4);
    __half2 h0 = __floats2half2_rn(a.x, a.y);
    __half2 h1 = __floats2half2_rn(a.z, a.w);
    __half2 h2 = __floats2half2_rn(b.x, b.y);
    __half2 h3 = __floats2half2_rn(b.z, b.w);
    uint4 u;
    u.x = *(uint32_t*)&h0; u.y = *(uint32_t*)&h1;
    u.z = *(uint32_t*)&h2; u.w = *(uint32_t*)&h3;
    *(uint4*)(g_xh + i) = u;
}

// ---------------------------------------------------------------------------
// Kernel 1: dequant int4 GPTQ -> fp16 fragment-ordered W (verified R10)
// ---------------------------------------------------------------------------
__global__ void dequant_kernel(const int* __restrict__ qweight,
                               const int* __restrict__ qzeros,
                               const void* __restrict__ scales_raw) {
    int pr = blockIdx.y;                       // 0..511
    int n  = blockIdx.x * 256 + threadIdx.x;   // 43*256 == 11008
    int g  = pr >> 4;

    const float* sf = (const float*)scales_raw;
    float probe = sf[0];
    bool is_f32 = (probe > 5e-4f && probe < 5e-2f);

    uint32_t q  = (uint32_t)qweight[(size_t)pr * N_DIM + n];
    uint32_t zq = (uint32_t)qzeros[(size_t)g * NPACK + (n >> 3)];
    float z = (float)((zq >> (4 * (n & 7))) & 15u);
    float s = is_f32 ? sf[(size_t)g * N_DIM + n]
                     : __half2float(((const __half*)scales_raw)[(size_t)g * N_DIM + n]);

    int tn    = n >> 3;
    int tk32  = pr >> 2;
    int j16   = (pr >> 1) & 1;
    int regsel= pr & 1;
    size_t base = (((size_t)tn * TK32 + tk32) * 32 + 4 * (n & 7)) * 8
                  + j16 * 4 + regsel * 2;

#pragma unroll
    for (int p = 0; p < 4; p++) {
        float w0 = ((float)((q >> (8 * p))     & 15u) - z) * s;
        float w1 = ((float)((q >> (8 * p + 4)) & 15u) - z) * s;
        *(__half2*)(g_wf + base + (size_t)p * 8) = __floats2half2_rn(w0, w1);
    }
}

// ---------------------------------------------------------------------------
// PTX helpers
// ---------------------------------------------------------------------------
__device__ __forceinline__ void ldmatrix_x4(uint32_t& r0, uint32_t& r1,
                                            uint32_t& r2, uint32_t& r3,
                                            uint32_t addr) {
    asm volatile("ldmatrix.sync.aligned.m8n8.x4.shared.b16 {%0,%1,%2,%3}, [%4];"
                 : "=r"(r0), "=r"(r1), "=r"(r2), "=r"(r3) : "r"(addr));
}
__device__ __forceinline__ void mma16816(float* c, const uint32_t* a,
                                         uint32_t b0, uint32_t b1) {
    asm volatile(
        "mma.sync.aligned.m16n8k16.row.col.f32.f16.f16.f32 "
        "{%0,%1,%2,%3}, {%4,%5,%6,%7}, {%8,%9}, {%0,%1,%2,%3};"
        : "+f"(c[0]), "+f"(c[1]), "+f"(c[2]), "+f"(c[3])
        : "r"(a[0]), "r"(a[1]), "r"(a[2]), "r"(a[3]), "r"(b0), "r"(b1));
}

// ---------------------------------------------------------------------------
// Kernel 2: HMMA GEMM. A via smem (double-buffered, one barrier/k-tile);
// B direct from fragment-ordered global, SINGLE register buffer (no spills).
// ---------------------------------------------------------------------------
__global__ __launch_bounds__(256, 2)
void gemm_kernel(float* __restrict__ out) {
    __shared__ __half As[2][BM * A_LD];

    const int tid  = threadIdx.x;
    const int lane = tid & 31;
    const int wid  = tid >> 5;
    const int warp_m = wid & 1;    // 0..1 (64 rows each)
    const int warp_n = wid >> 1;   // 0..3 (32 cols each)

    // 8-M-supertile rasterization keeps the B slice L2-resident per wave
    const int bid = blockIdx.x;
    const int grp = bid / (8 * NT_TILES);
    const int rem = bid % (8 * NT_TILES);
    const int mt  = grp * 8 + (rem & 7);
    const int nt  = rem >> 3;
    const int m0 = mt * BM;
    const int n0 = nt * BN;

    const __half* asrc = g_xh + (size_t)m0 * K_DIM;

    // Single B base pointer; per-nh stride = TK32*32 uint4 (64KB), a
    // compile-time constant foldable into LDG immediate offsets.
    const int tn0 = (n0 >> 3) + warp_n * 4;
    const uint4* bbase = (const uint4*)(g_wf +
                         ((size_t)tn0 * TK32 * 32 + lane) * 8);
    const int NHSTRIDE = TK32 * 32;   // 4096 uint4 per nh step

    // A load coords: 128 rows x 4 chunks of 16B, 2 per thread
    const int ar = tid >> 2, ac = tid & 3;
    uint4 areg[2];

    auto loadA = [&](int kt) {
        const int k0 = kt * BK;
#pragma unroll
        for (int i = 0; i < 2; i++)
            areg[i] = *(const uint4*)(asrc + (size_t)(ar + i * 64) * K_DIM + k0 + ac * 8);
    };
    auto storeA = [&](int buf) {
#pragma unroll
        for (int i = 0; i < 2; i++)
            *(uint4*)(&As[buf][(ar + i * 64) * A_LD + ac * 8]) = areg[i];
    };

    uint4 bf[4];
    auto loadB = [&](int kt) {
        const uint4* p = bbase + (size_t)kt * 32;   // 512B per k-tile
#pragma unroll
        for (int nh = 0; nh < 4; nh++)
            bf[nh] = p[nh * NHSTRIDE];
    };

    float acc[4][4][4];
#pragma unroll
    for (int i = 0; i < 4; i++)
#pragma unroll
        for (int j = 0; j < 4; j++) {
            acc[i][j][0] = 0.f; acc[i][j][1] = 0.f;
            acc[i][j][2] = 0.f; acc[i][j][3] = 0.f;
        }

    const uint32_t sbase = (uint32_t)__cvta_generic_to_shared(&As[0][0]);

    auto compute = [&](int buf) {
        const uint32_t abase = sbase + buf * (BM * A_LD * 2);
#pragma unroll
        for (int ks = 0; ks < 2; ks++) {
            const int kk = ks * 16;
            uint32_t a[4][4];
#pragma unroll
            for (int mi = 0; mi < 4; mi++) {
                int row = warp_m * 64 + mi * 16 + (lane & 15);
                int col = kk + 8 * (lane >> 4);
                ldmatrix_x4(a[mi][0], a[mi][1], a[mi][2], a[mi][3],
                            abase + (row * A_LD + col) * 2);
            }
#pragma unroll
            for (int mi = 0; mi < 4; mi++)
#pragma unroll
                for (int nh = 0; nh < 4; nh++) {
                    uint32_t b0 = ks ? bf[nh].z : bf[nh].x;
                    uint32_t b1 = ks ? bf[nh].w : bf[nh].y;
                    mma16816(acc[mi][nh], a[mi], b0, b1);
                }
        }
    };

    // Prologue: buf0 <- A tile0; regs <- A tile1; bf <- B tile0
    loadA(0); storeA(0); loadA(1); loadB(0);
    __syncthreads();

    // Steady state: ONE barrier per k-tile. bf reloaded AFTER its last use.
#pragma unroll 1
    for (int t = 0; t < NT; t++) {
        const int cur = t & 1, nxt = cur ^ 1;
        if (t + 1 < NT) storeA(nxt);
        if (t + 2 < NT) loadA(t + 2);
        compute(cur);
        if (t + 1 < NT) loadB(t + 1);
        __syncthreads();
    }

    // Epilogue: round through fp16, write float2
    const int g4 = lane >> 2, t4 = lane & 3;
#pragma unroll
    for (int mi = 0; mi < 4; mi++) {
#pragma unroll
        for (int nh = 0; nh < 4; nh++) {
            int row = m0 + warp_m * 64 + mi * 16 + g4;
            int col = n0 + warp_n * 32 + nh * 8 + t4 * 2;
            float2 v0, v1;
            v0.x = __half2float(__float2half_rn(acc[mi][nh][0]));
            v0.y = __half2float(__float2half_rn(acc[mi][nh][1]));
            v1.x = __half2float(__float2half_rn(acc[mi][nh][2]));
            v1.y = __half2float(__float2half_rn(acc[mi][nh][3]));
            *(float2*)(out + (size_t)row * N_DIM + col)       = v0;
            *(float2*)(out + (size_t)(row + 8) * N_DIM + col) = v1;
        }
    }
}

// ---------------------------------------------------------------------------
extern "C" void kernel_launch(void* const* d_in, const int* in_sizes, int n_in,
                              void* d_out, int out_size) {
    const float* x       = (const float*)d_in[0];
    const int*   qweight = (const int*)d_in[1];
    const int*   qzeros  = (const int*)d_in[2];
    const void*  scales  = d_in[3];
    float* out = (float*)d_out;

    convert_x<<<16384, 256>>>(x);
    dequant_kernel<<<dim3(43, KPACK), 256>>>(qweight, qzeros, scales);

    gemm_kernel<<<MT_TILES * NT_TILES, 256>>>(out);
}

// round 13
// speedup vs baseline: 2.0511x; 1.3252x over previous
#include <cuda_runtime.h>
#include <cuda_fp16.h>
#include <cstdint>
#include <cstddef>

// Problem constants
#define M_DIM 8192
#define K_DIM 4096
#define N_DIM 11008
#define NPACK (N_DIM / 8)
#define KPACK (K_DIM / 8)

#define TK16 (K_DIM / 16)      // 256 k16-tiles
#define TK32 (K_DIM / 32)      // 128 k32-tiles

// GEMM tiling: block 128x128x32, 8 warps (2M x 4N), warp tile 64x32
#define BM 128
#define BN 128
#define BK 32
#define NT (K_DIM / BK)        // 128
#define MT_TILES (M_DIM / BM)  // 64
#define NT_TILES (N_DIM / BN)  // 86

// Device scratch (allocation-free rule)
// A in mma-fragment order: [tm16][tk16][lane]{a0,a1,a2,a3} (16B per lane)
__device__ __half g_af[(size_t)M_DIM * K_DIM];
// W in mma-fragment order: [tn8][tk32][lane]{b0_k16a,b1_k16a,b0_k16b,b1_k16b}
__device__ __half g_wf[(size_t)K_DIM * N_DIM];

// ---------------------------------------------------------------------------
// Kernel 0: x fp32 -> fp16 in A-fragment order.
// mma.m16n8k16 A-lane map: lane l -> r = l>>2 (0..7), c = l&3.
//   a0 = (r,   2c),(r,   2c+1)   a1 = (r+8, 2c),(r+8, 2c+1)
//   a2 = (r,   2c+8),(r, 2c+9)   a3 = (r+8, 2c+8),(r+8, 2c+9)
// One thread builds one lane's 16B: 4 float2 loads (32B-sector efficient),
// one STG.128 (warp-coalesced).
// ---------------------------------------------------------------------------
__global__ void convert_x(const float* __restrict__ x) {
    const int tm   = blockIdx.x;              // 0..511
    const int lane = threadIdx.x & 31;
    const int tkb  = threadIdx.x >> 5;        // 0..7
    const int r = lane >> 2, c = lane & 3;
    const int m0 = tm * 16;

    const float* row0 = x + (size_t)(m0 + r) * K_DIM + 2 * c;
    const float* row8 = row0 + (size_t)8 * K_DIM;
    uint4* dst = (uint4*)g_af + ((size_t)tm * TK16) * 32 + lane;

#pragma unroll 4
    for (int tk16 = tkb; tk16 < TK16; tk16 += 8) {
        const int k0 = tk16 * 16;
        float2 f0 = *(const float2*)(row0 + k0);
        float2 f1 = *(const float2*)(row8 + k0);
        float2 f2 = *(const float2*)(row0 + k0 + 8);
        float2 f3 = *(const float2*)(row8 + k0 + 8);
        __half2 h0 = __floats2half2_rn(f0.x, f0.y);
        __half2 h1 = __floats2half2_rn(f1.x, f1.y);
        __half2 h2 = __floats2half2_rn(f2.x, f2.y);
        __half2 h3 = __floats2half2_rn(f3.x, f3.y);
        uint4 u;
        u.x = *(uint32_t*)&h0; u.y = *(uint32_t*)&h1;
        u.z = *(uint32_t*)&h2; u.w = *(uint32_t*)&h3;
        dst[(size_t)tk16 * 32] = u;
    }
}

// ---------------------------------------------------------------------------
// Kernel 1: dequant int4 GPTQ -> fp16 fragment-ordered W (verified R10/R12)
// ---------------------------------------------------------------------------
__global__ void dequant_kernel(const int* __restrict__ qweight,
                               const int* __restrict__ qzeros,
                               const void* __restrict__ scales_raw) {
    int pr = blockIdx.y;                       // 0..511
    int n  = blockIdx.x * 256 + threadIdx.x;   // 43*256 == 11008
    int g  = pr >> 4;

    const float* sf = (const float*)scales_raw;
    float probe = sf[0];
    bool is_f32 = (probe > 5e-4f && probe < 5e-2f);

    uint32_t q  = (uint32_t)qweight[(size_t)pr * N_DIM + n];
    uint32_t zq = (uint32_t)qzeros[(size_t)g * NPACK + (n >> 3)];
    float z = (float)((zq >> (4 * (n & 7))) & 15u);
    float s = is_f32 ? sf[(size_t)g * N_DIM + n]
                     : __half2float(((const __half*)scales_raw)[(size_t)g * N_DIM + n]);

    int tn    = n >> 3;
    int tk32  = pr >> 2;
    int j16   = (pr >> 1) & 1;
    int regsel= pr & 1;
    size_t base = (((size_t)tn * TK32 + tk32) * 32 + 4 * (n & 7)) * 8
                  + j16 * 4 + regsel * 2;

#pragma unroll
    for (int p = 0; p < 4; p++) {
        float w0 = ((float)((q >> (8 * p))     & 15u) - z) * s;
        float w1 = ((float)((q >> (8 * p + 4)) & 15u) - z) * s;
        *(__half2*)(g_wf + base + (size_t)p * 8) = __floats2half2_rn(w0, w1);
    }
}

// ---------------------------------------------------------------------------
// mma helper
// ---------------------------------------------------------------------------
__device__ __forceinline__ void mma16816(float* c, uint32_t a0, uint32_t a1,
                                         uint32_t a2, uint32_t a3,
                                         uint32_t b0, uint32_t b1) {
    asm volatile(
        "mma.sync.aligned.m16n8k16.row.col.f32.f16.f16.f32 "
        "{%0,%1,%2,%3}, {%4,%5,%6,%7}, {%8,%9}, {%0,%1,%2,%3};"
        : "+f"(c[0]), "+f"(c[1]), "+f"(c[2]), "+f"(c[3])
        : "r"(a0), "r"(a1), "r"(a2), "r"(a3), "r"(b0), "r"(b1));
}

// ---------------------------------------------------------------------------
// Kernel 2: pure fragment GEMM — no smem, no barriers.
// Per warp per k-tile: 8 A-frag LDG.128 + 4 B-frag LDG.128 + 32 HMMA.
// ---------------------------------------------------------------------------
__global__ __launch_bounds__(256, 2)
void gemm_kernel(float* __restrict__ out) {
    const int tid  = threadIdx.x;
    const int lane = tid & 31;
    const int wid  = tid >> 5;
    const int warp_m = wid & 1;    // 0..1 (64 rows = 4 m16 tiles each)
    const int warp_n = wid >> 1;   // 0..3 (32 cols = 4 n8 tiles each)

    // 8-M-supertile rasterization keeps the B slice L2-resident per wave
    const int bid = blockIdx.x;
    const int grp = bid / (8 * NT_TILES);
    const int rem = bid % (8 * NT_TILES);
    const int mt  = grp * 8 + (rem & 7);
    const int nt  = rem >> 3;
    const int m0 = mt * BM;
    const int n0 = nt * BN;

    // A fragment base: tm0 = first m16 tile of this warp
    const int tm0 = (m0 >> 4) + warp_m * 4;
    const uint4* aptr = (const uint4*)g_af + ((size_t)tm0 * TK16) * 32 + lane;
    const int AMI = TK16 * 32;    // uint4 stride per m16 tile (8192)

    // B fragment base
    const int tn0 = (n0 >> 3) + warp_n * 4;
    const uint4* bptr = (const uint4*)g_wf + ((size_t)tn0 * TK32) * 32 + lane;
    const int BNH = TK32 * 32;    // uint4 stride per n8 tile (4096)

    float acc[4][4][4];
#pragma unroll
    for (int i = 0; i < 4; i++)
#pragma unroll
        for (int j = 0; j < 4; j++) {
            acc[i][j][0] = 0.f; acc[i][j][1] = 0.f;
            acc[i][j][2] = 0.f; acc[i][j][3] = 0.f;
        }

#pragma unroll 1
    for (int t = 0; t < NT; t++) {
        // ---- loads (12x LDG.128, MLP=12) ----
        uint4 af[2][4];   // [ks][mi]
        uint4 bf[4];      // [nh]
        const int tkoff0 = (2 * t) * 32, tkoff1 = (2 * t + 1) * 32;
#pragma unroll
        for (int mi = 0; mi < 4; mi++)
            af[0][mi] = aptr[mi * AMI + tkoff0];
#pragma unroll
        for (int nh = 0; nh < 4; nh++)
            bf[nh] = bptr[nh * BNH + t * 32];
#pragma unroll
        for (int mi = 0; mi < 4; mi++)
            af[1][mi] = aptr[mi * AMI + tkoff1];

        // ---- 32 HMMA ----
#pragma unroll
        for (int mi = 0; mi < 4; mi++)
#pragma unroll
            for (int nh = 0; nh < 4; nh++)
                mma16816(acc[mi][nh], af[0][mi].x, af[0][mi].y,
                         af[0][mi].z, af[0][mi].w, bf[nh].x, bf[nh].y);
#pragma unroll
        for (int mi = 0; mi < 4; mi++)
#pragma unroll
            for (int nh = 0; nh < 4; nh++)
                mma16816(acc[mi][nh], af[1][mi].x, af[1][mi].y,
                         af[1][mi].z, af[1][mi].w, bf[nh].z, bf[nh].w);
    }

    // Epilogue: round through fp16, write float2
    const int g4 = lane >> 2, t4 = lane & 3;
#pragma unroll
    for (int mi = 0; mi < 4; mi++) {
#pragma unroll
        for (int nh = 0; nh < 4; nh++) {
            int row = m0 + warp_m * 64 + mi * 16 + g4;
            int col = n0 + warp_n * 32 + nh * 8 + t4 * 2;
            float2 v0, v1;
            v0.x = __half2float(__float2half_rn(acc[mi][nh][0]));
            v0.y = __half2float(__float2half_rn(acc[mi][nh][1]));
            v1.x = __half2float(__float2half_rn(acc[mi][nh][2]));
            v1.y = __half2float(__float2half_rn(acc[mi][nh][3]));
            *(float2*)(out + (size_t)row * N_DIM + col)       = v0;
            *(float2*)(out + (size_t)(row + 8) * N_DIM + col) = v1;
        }
    }
}

// ---------------------------------------------------------------------------
extern "C" void kernel_launch(void* const* d_in, const int* in_sizes, int n_in,
                              void* d_out, int out_size) {
    const float* x       = (const float*)d_in[0];
    const int*   qweight = (const int*)d_in[1];
    const int*   qzeros  = (const int*)d_in[2];
    const void*  scales  = d_in[3];
    float* out = (float*)d_out;

    convert_x<<<M_DIM / 16, 256>>>(x);
    dequant_kernel<<<dim3(43, KPACK), 256>>>(qweight, qzeros, scales);

    gemm_kernel<<<MT_TILES * NT_TILES, 256>>>(out);
}